// round 1
// baseline (speedup 1.0000x reference)
#include <cuda_runtime.h>

// Problem constants
#define PB 64
#define PS 4096
#define PD 256
#define PL 16

// Tiling
#define TM 128
#define TN 128
#define KB 16
#define SPAD 4
#define SSTR (TM + SPAD)   // 132 floats per smem row (528B, 16B-aligned)

__device__ __forceinline__ unsigned long long pack2(float lo, float hi) {
    unsigned long long r;
    asm("mov.b64 %0, {%1, %2};" : "=l"(r) : "f"(lo), "f"(hi));
    return r;
}

__device__ __forceinline__ void fma2(unsigned long long& d,
                                     unsigned long long a,
                                     unsigned long long b) {
    asm("fma.rn.f32x2 %0, %1, %2, %0;" : "+l"(d) : "l"(a), "l"(b));
}

__global__ __launch_bounds__(256, 2)
void mm_f32x2_kernel(const float* __restrict__ X,
                     const float* __restrict__ Wmap,
                     const int* __restrict__ pair_id,
                     float* __restrict__ out) {
    const int b  = blockIdx.z;
    const int s0 = blockIdx.x * TM;
    const int e0 = blockIdx.y * TN;
    const int tid = threadIdx.x;

    int lang = pair_id[b];

    const float* __restrict__ Xb = X   + ((long long)b * PS + s0) * PD;
    float* __restrict__       Ob = out + ((long long)b * PS + s0) * PD;

    // ---------------- passthrough: out = X for this tile ----------------
    if (lang < 0) {
        #pragma unroll 4
        for (int it = 0; it < 16; ++it) {
            int q = it * 256 + tid;      // 0..4095 float4s in a 128x128 tile
            int m = q >> 5;              // row (128 rows, 32 float4/row)
            int c = q & 31;
            float4 v = ((const float4*)(Xb + (long long)m * PD + e0))[c];
            ((float4*)(Ob + (long long)m * PD + e0))[c] = v;
        }
        return;
    }
    if (lang >= PL) lang = PL - 1;

    const float* __restrict__ Wl =
        Wmap + ((long long)lang * PD + e0) * PD;

    __shared__ __align__(16) float Xs[2][KB][SSTR];
    __shared__ __align__(16) float Ws[2][KB][SSTR];

    const int tx = tid & 15;       // N direction
    const int ty = tid >> 4;       // M direction
    const int m8 = ty * 8;
    const int n8 = tx * 8;

    // acc[i][j] = packed f32x2 for output rows (m8+2i, m8+2i+1), col n8+j
    unsigned long long acc[4][8];
    #pragma unroll
    for (int i = 0; i < 4; ++i)
        #pragma unroll
        for (int j = 0; j < 8; ++j)
            acc[i][j] = 0ULL;   // bit pattern of (0.0f, 0.0f)

    // ---- tile loader: global (row-major, d contiguous) -> smem [k][row] ----
    // 512 float4 per operand per chunk; each thread does 2.
    auto load_tile = [&](int kb, int buf) {
        #pragma unroll
        for (int h = 0; h < 2; ++h) {
            int q   = h * 256 + tid;     // 0..511
            int row = q >> 2;            // 0..127
            int kq  = (q & 3) * 4;       // 0,4,8,12
            float4 xv = *(const float4*)(Xb + (long long)row * PD + kb + kq);
            float4 wv = *(const float4*)(Wl + (long long)row * PD + kb + kq);
            Xs[buf][kq + 0][row] = xv.x;
            Xs[buf][kq + 1][row] = xv.y;
            Xs[buf][kq + 2][row] = xv.z;
            Xs[buf][kq + 3][row] = xv.w;
            Ws[buf][kq + 0][row] = wv.x;
            Ws[buf][kq + 1][row] = wv.y;
            Ws[buf][kq + 2][row] = wv.z;
            Ws[buf][kq + 3][row] = wv.w;
        }
    };

    load_tile(0, 0);
    __syncthreads();

    for (int kb = 0; kb < PD; kb += KB) {
        const int buf = (kb / KB) & 1;
        if (kb + KB < PD) load_tile(kb + KB, buf ^ 1);

        #pragma unroll
        for (int k = 0; k < KB; ++k) {
            const float* xr = &Xs[buf][k][m8];
            const float* wr = &Ws[buf][k][n8];

            // 8 consecutive M values -> 4 packed f32x2 (two 16B loads)
            ulonglong2 xa = *(const ulonglong2*)(xr);
            ulonglong2 xb2 = *(const ulonglong2*)(xr + 4);
            unsigned long long xp[4] = { xa.x, xa.y, xb2.x, xb2.y };

            float4 wa = *(const float4*)(wr);
            float4 wb = *(const float4*)(wr + 4);
            unsigned long long wd[8];
            wd[0] = pack2(wa.x, wa.x);
            wd[1] = pack2(wa.y, wa.y);
            wd[2] = pack2(wa.z, wa.z);
            wd[3] = pack2(wa.w, wa.w);
            wd[4] = pack2(wb.x, wb.x);
            wd[5] = pack2(wb.y, wb.y);
            wd[6] = pack2(wb.z, wb.z);
            wd[7] = pack2(wb.w, wb.w);

            #pragma unroll
            for (int i = 0; i < 4; ++i)
                #pragma unroll
                for (int j = 0; j < 8; ++j)
                    fma2(acc[i][j], xp[i], wd[j]);
        }
        __syncthreads();
    }

    // ---------------- epilogue: unpack and store ----------------
    #pragma unroll
    for (int i = 0; i < 4; ++i) {
        float lo[8], hi[8];
        #pragma unroll
        for (int j = 0; j < 8; ++j) {
            float2 f = *reinterpret_cast<float2*>(&acc[i][j]);
            lo[j] = f.x;
            hi[j] = f.y;
        }
        float* o0 = Ob + (long long)(m8 + 2 * i) * PD + e0 + n8;
        float* o1 = o0 + PD;
        ((float4*)o0)[0] = make_float4(lo[0], lo[1], lo[2], lo[3]);
        ((float4*)o0)[1] = make_float4(lo[4], lo[5], lo[6], lo[7]);
        ((float4*)o1)[0] = make_float4(hi[0], hi[1], hi[2], hi[3]);
        ((float4*)o1)[1] = make_float4(hi[4], hi[5], hi[6], hi[7]);
    }
}

extern "C" void kernel_launch(void* const* d_in, const int* in_sizes, int n_in,
                              void* d_out, int out_size) {
    const float* X    = (const float*)d_in[0];   // right_emb (B,S,D) f32
    const float* Wmap = (const float*)d_in[1];   // mapping (L,D,D) f32
    const int*   pid  = (const int*)d_in[2];     // pair_id (B,1) i32

    dim3 grid(PS / TM, PD / TN, PB);   // (32, 2, 64)
    mm_f32x2_kernel<<<grid, 256>>>(X, Wmap, pid, (float*)d_out);
}

// round 3
// speedup vs baseline: 2.6694x; 2.6694x over previous
#include <cuda_runtime.h>
#include <cuda_bf16.h>
#include <cstdint>

// Problem constants
#define PB 64
#define PS 4096
#define PD 256
#define PL 16

// Tiling
#define TM 128
#define TN 128
#define KC 64
#define NCHUNK (PD / KC)   // 4
#define THREADS 256

// smem: 4 tiles (A hi/lo, B hi/lo), each 128 rows x 128 bytes (64 bf16)
#define TILE_SZ (128 * 128)
#define SMEM_BYTES (4 * TILE_SZ)   // 65536

__device__ __forceinline__ uint32_t smem_u32(const void* p) {
    uint32_t a;
    asm("{ .reg .u64 t; cvta.to.shared.u64 t, %1; cvt.u32.u64 %0, t; }"
        : "=r"(a) : "l"(p));
    return a;
}

#define LDSM4(R0, R1, R2, R3, A)                                             \
    asm volatile("ldmatrix.sync.aligned.m8n8.x4.shared.b16 {%0,%1,%2,%3}, [%4];" \
                 : "=r"(R0), "=r"(R1), "=r"(R2), "=r"(R3) : "r"(A))

__device__ __forceinline__ void mma16816(float* d, const uint32_t* a,
                                         const uint32_t* b) {
    asm volatile(
        "mma.sync.aligned.m16n8k16.row.col.f32.bf16.bf16.f32 "
        "{%0,%1,%2,%3}, {%4,%5,%6,%7}, {%8,%9}, {%0,%1,%2,%3};"
        : "+f"(d[0]), "+f"(d[1]), "+f"(d[2]), "+f"(d[3])
        : "r"(a[0]), "r"(a[1]), "r"(a[2]), "r"(a[3]), "r"(b[0]), "r"(b[1]));
}

__device__ __forceinline__ void sts64(uint32_t addr, uint32_t a, uint32_t b) {
    asm volatile("st.shared.v2.b32 [%0], {%1, %2};" :: "r"(addr), "r"(a), "r"(b));
}

// hi = bf16_rn(x) for (a,b); lo = bf16_rn(residual)
__device__ __forceinline__ void cvt_pair(float a, float b, uint32_t& hi, uint32_t& lo) {
    __nv_bfloat162 h = __floats2bfloat162_rn(a, b);
    float2 hf = __bfloat1622float2(h);
    __nv_bfloat162 l = __floats2bfloat162_rn(a - hf.x, b - hf.y);
    hi = *reinterpret_cast<uint32_t*>(&h);
    lo = *reinterpret_cast<uint32_t*>(&l);
}

// swizzled byte offset for (row, 16B-chunk c) in a 128B-row tile
__device__ __forceinline__ uint32_t swz(int row, int c) {
    return (uint32_t)(row * 128 + (((c ^ (row & 7)) << 4)));
}

__global__ __launch_bounds__(THREADS, 2)
void mm_hmma_kernel(const float* __restrict__ X,
                    const float* __restrict__ Wmap,
                    const int* __restrict__ pid,
                    float* __restrict__ out) {
    extern __shared__ char smem[];
    const int b  = blockIdx.z;
    const int s0 = blockIdx.x * TM;
    const int e0 = blockIdx.y * TN;
    const int tid = threadIdx.x;
    const int wid = tid >> 5;
    const int lid = tid & 31;

    int lang = pid[b];
    const float* __restrict__ Xb = X   + ((size_t)b * PS + s0) * PD;
    float* __restrict__       Ob = out + ((size_t)b * PS + s0) * PD;

    // ---------------- passthrough ----------------
    if (lang < 0) {
        #pragma unroll 4
        for (int i = 0; i < 16; ++i) {
            int idx = i * THREADS + tid;     // 4096 float4 in 128x128 tile
            int r = idx >> 5;
            int c = idx & 31;
            ((float4*)(Ob + (size_t)r * PD + e0))[c] =
                ((const float4*)(Xb + (size_t)r * PD + e0))[c];
        }
        return;
    }
    if (lang >= PL) lang = PL - 1;
    const float* __restrict__ Wl = Wmap + (size_t)lang * PD * PD + (size_t)e0 * PD;

    const uint32_t sb  = smem_u32(smem);
    const uint32_t aHi = sb;
    const uint32_t aLo = sb + TILE_SZ;
    const uint32_t bHi = sb + 2 * TILE_SZ;
    const uint32_t bLo = sb + 3 * TILE_SZ;

    // warp layout: 2 (M) x 4 (N); warp tile 64 x 32
    const int m0 = (wid & 1) * 64;
    const int n0 = (wid >> 1) * 32;

    float acc[4][4][4];
    #pragma unroll
    for (int f = 0; f < 4; ++f)
        #pragma unroll
        for (int g = 0; g < 4; ++g)
            #pragma unroll
            for (int q = 0; q < 4; ++q) acc[f][g][q] = 0.f;

    for (int ch = 0; ch < NCHUNK; ++ch) {
        const int kb = ch * KC;

        // ---- load + convert + store (A then B), 8 float4 each per thread ----
        #pragma unroll
        for (int i = 0; i < 8; ++i) {
            int idx = i * THREADS + tid;        // 2048 float4
            int r  = idx >> 4;                  // 0..127
            int k4 = (idx & 15) * 4;            // 0..60
            float4 v = *(const float4*)(Xb + (size_t)r * PD + kb + k4);
            uint32_t h0, l0, h1, l1;
            cvt_pair(v.x, v.y, h0, l0);
            cvt_pair(v.z, v.w, h1, l1);
            uint32_t off = swz(r, k4 >> 3) + ((k4 & 7) << 1);
            sts64(aHi + off, h0, h1);
            sts64(aLo + off, l0, l1);
        }
        #pragma unroll
        for (int i = 0; i < 8; ++i) {
            int idx = i * THREADS + tid;
            int r  = idx >> 4;
            int k4 = (idx & 15) * 4;
            float4 v = *(const float4*)(Wl + (size_t)r * PD + kb + k4);
            uint32_t h0, l0, h1, l1;
            cvt_pair(v.x, v.y, h0, l0);
            cvt_pair(v.z, v.w, h1, l1);
            uint32_t off = swz(r, k4 >> 3) + ((k4 & 7) << 1);
            sts64(bHi + off, h0, h1);
            sts64(bLo + off, l0, l1);
        }
        __syncthreads();

        // ---- 4 k16 steps ----
        #pragma unroll
        for (int ks = 0; ks < 4; ++ks) {
            uint32_t ah[4][4], al[4][4];
            #pragma unroll
            for (int f = 0; f < 4; ++f) {
                int r = m0 + f * 16 + (lid & 15);
                int c = ks * 2 + (lid >> 4);
                uint32_t off = swz(r, c);
                LDSM4(ah[f][0], ah[f][1], ah[f][2], ah[f][3], aHi + off);
                LDSM4(al[f][0], al[f][1], al[f][2], al[f][3], aLo + off);
            }
            uint32_t bh[4][2], bl[4][2];
            #pragma unroll
            for (int g2 = 0; g2 < 2; ++g2) {
                int r = n0 + g2 * 16 + (lid & 7) + ((lid >> 4) << 3);
                int c = ks * 2 + ((lid >> 3) & 1);
                uint32_t off = swz(r, c);
                LDSM4(bh[2 * g2][0], bh[2 * g2][1],
                      bh[2 * g2 + 1][0], bh[2 * g2 + 1][1], bHi + off);
                LDSM4(bl[2 * g2][0], bl[2 * g2][1],
                      bl[2 * g2 + 1][0], bl[2 * g2 + 1][1], bLo + off);
            }
            #pragma unroll
            for (int f = 0; f < 4; ++f)
                #pragma unroll
                for (int g = 0; g < 4; ++g) {
                    mma16816(acc[f][g], ah[f], bh[g]);
                    mma16816(acc[f][g], ah[f], bl[g]);
                    mma16816(acc[f][g], al[f], bh[g]);
                }
        }
        __syncthreads();
    }

    // ---------------- epilogue ----------------
    const int tr = lid >> 2;          // 0..7
    const int tc = (lid & 3) * 2;     // 0,2,4,6
    #pragma unroll
    for (int f = 0; f < 4; ++f) {
        #pragma unroll
        for (int g = 0; g < 4; ++g) {
            int row = m0 + f * 16 + tr;
            int col = e0 + n0 + g * 8 + tc;
            float* p0 = Ob + (size_t)row * PD + col;
            *(float2*)p0            = make_float2(acc[f][g][0], acc[f][g][1]);
            *(float2*)(p0 + 8 * PD) = make_float2(acc[f][g][2], acc[f][g][3]);
        }
    }
}

extern "C" void kernel_launch(void* const* d_in, const int* in_sizes, int n_in,
                              void* d_out, int out_size) {
    const float* X    = (const float*)d_in[0];   // right_emb (B,S,D) f32
    const float* Wmap = (const float*)d_in[1];   // mapping (L,D,D) f32
    const int*   pid  = (const int*)d_in[2];     // pair_id (B,1) i32

    cudaFuncSetAttribute(mm_hmma_kernel,
                         cudaFuncAttributeMaxDynamicSharedMemorySize, SMEM_BYTES);
    dim3 grid(PS / TM, PD / TN, PB);   // (32, 2, 64)
    mm_hmma_kernel<<<grid, THREADS, SMEM_BYTES>>>(X, Wmap, pid, (float*)d_out);
}